// round 15
// baseline (speedup 1.0000x reference)
#include <cuda_runtime.h>

// exp(-d2 / (2*0.3^2)) = exp2(-K * d2), K = log2(e) / 0.18
#define KCONST 8.014972449383130f
#define BLOCK 352
#define PTS 2
#define NSPLIT 2
#define NPMAX 131072   // >= n (n = 100000 for this problem)
#define NSM 148        // GB300 SM count

typedef unsigned long long u64;

// partial RBF sums: [half][point] as float4 {u,v,w,pad}
__device__ float4 g_partial[NSPLIT * NPMAX];
// per point-block arrival counters (zero-init; finisher resets -> replay-safe)
__device__ int g_count[1024];

__device__ __forceinline__ u64 fma2(u64 a, u64 b, u64 c) {
    u64 d;
    asm("fma.rn.f32x2 %0, %1, %2, %3;" : "=l"(d) : "l"(a), "l"(b), "l"(c));
    return d;
}
__device__ __forceinline__ u64 add2(u64 a, u64 b) {
    u64 d;
    asm("add.rn.f32x2 %0, %1, %2;" : "=l"(d) : "l"(a), "l"(b));
    return d;
}
__device__ __forceinline__ u64 pack2(float lo, float hi) {
    u64 d;
    asm("mov.b64 %0, {%1, %2};" : "=l"(d) : "f"(lo), "f"(hi));
    return d;
}
__device__ __forceinline__ void unpack2(u64 v, float& lo, float& hi) {
    asm("mov.b64 {%0, %1}, %2;" : "=f"(lo), "=f"(hi) : "l"(v));
}
// fp32 ex2 on both packed lanes (R6-proven: rel_err ~1.5e-6)
__device__ __forceinline__ u64 ex2_pair(u64 t) {
    u64 e;
    asm("{\n\t"
        ".reg .f32 e0, e1;\n\t"
        "mov.b64 {e0, e1}, %1;\n\t"
        "ex2.approx.ftz.f32 e0, e0;\n\t"
        "ex2.approx.ftz.f32 e1, e1;\n\t"
        "mov.b64 %0, {e0, e1};\n\t"
        "}" : "=l"(e) : "l"(t));
    return e;
}

// Packed-lane = 2 adjacent CENTERS. Per pair p: 56 B
//   sA[p] = {c0x,c1x, c0y,c1y}
//   sB[p] = {c0z,c1z, cs0,cs1}    cs = -K*|c|^2
//   sQ[p] = {u0,u1,  v0,v1}
//   sW[p] = {w0,w1}
__global__ __launch_bounds__(BLOCK, NSPLIT)
void rbf_kernel(const float* __restrict__ x, const float* __restrict__ cen,
                const float* __restrict__ cu, const float* __restrict__ cv,
                const float* __restrict__ cw, float* __restrict__ out,
                int n, int m, int Ph, int gridP, int tot)
{
    extern __shared__ float4 sm[];
    float4* sA = sm;
    float4* sB = sm + Ph;
    float4* sQ = sm + 2 * Ph;
    float2* sW = (float2*)(sm + 3 * Ph);

    int pb    = blockIdx.x % gridP;   // point-block
    int half  = blockIdx.x / gridP;   // which center half
    int pbase = half * Ph;            // first center-pair of this half

    for (int p = threadIdx.x; p < Ph; p += BLOCK) {
        int gp = pbase + p;
        float c[2][3], cs[2], qu[2], qv[2], qw[2];
#pragma unroll
        for (int h = 0; h < 2; h++) {
            int e = 2 * gp + h;
            if (e < m) {
                c[h][0] = cen[3*e]; c[h][1] = cen[3*e+1]; c[h][2] = cen[3*e+2];
                cs[h] = -KCONST * (c[h][0]*c[h][0] + c[h][1]*c[h][1] + c[h][2]*c[h][2]);
                qu[h] = cu[e]; qv[h] = cv[e]; qw[h] = cw[e];
            } else {
                // pad: exponent -> -1e30 => ex2 -> 0; coeffs 0 => no contribution
                c[h][0] = c[h][1] = c[h][2] = 0.f;
                cs[h] = -1e30f;
                qu[h] = qv[h] = qw[h] = 0.f;
            }
        }
        sA[p] = make_float4(c[0][0], c[1][0], c[0][1], c[1][1]);
        sB[p] = make_float4(c[0][2], c[1][2], cs[0], cs[1]);
        sQ[p] = make_float4(qu[0], qu[1], qv[0], qv[1]);
        sW[p] = make_float2(qw[0], qw[1]);
    }
    __syncthreads();

    int g = pb * BLOCK + threadIdx.x;

    float px[PTS], py[PTS], pz[PTS], xs[PTS];
    u64 a0p[PTS], a1p[PTS], a2p[PTS], bbp[PTS];
#pragma unroll
    for (int s = 0; s < PTS; s++) {
        int i = g + s * tot;
        int ic = (i < n) ? i : 0;     // clamp loads; stores guarded below
        float x0 = x[3*ic], x1 = x[3*ic+1], x2 = x[3*ic+2];
        px[s] = x0; py[s] = x1; pz[s] = x2;
        float xsq = x0*x0 + x1*x1 + x2*x2;
        xs[s] = xsq;
        float a0 = 2.f * KCONST * x0;
        float a1 = 2.f * KCONST * x1;
        float a2 = 2.f * KCONST * x2;
        float bb = -KCONST * xsq;
        a0p[s] = pack2(a0, a0);
        a1p[s] = pack2(a1, a1);
        a2p[s] = pack2(a2, a2);
        bbp[s] = pack2(bb, bb);
    }

    u64 su[PTS], sv[PTS], sw[PTS];   // packed over the 2 center lanes
#pragma unroll
    for (int s = 0; s < PTS; s++) { su[s] = 0; sv[s] = 0; sw[s] = 0; }

    const ulonglong2* pA = (const ulonglong2*)sA;
    const ulonglong2* pB = (const ulonglong2*)sB;
    const ulonglong2* pQ = (const ulonglong2*)sQ;
    const u64*        pW = (const u64*)sW;

#pragma unroll 2
    for (int p = 0; p < Ph; p++) {
        ulonglong2 cxy = pA[p];   // .x = {c0x,c1x}, .y = {c0y,c1y}
        ulonglong2 czs = pB[p];   // .x = {c0z,c1z}, .y = {cs0,cs1}
        ulonglong2 quv = pQ[p];   // .x = {u0,u1},   .y = {v0,v1}
        u64        qw  = pW[p];   // {w0,w1}

#pragma unroll
        for (int s = 0; s < PTS; s++) {
            // t = 2K*x.c - K|x|^2 - K|c|^2  (packed over 2 centers)
            u64 t = add2(czs.y, bbp[s]);
            t = fma2(a2p[s], czs.x, t);
            t = fma2(a1p[s], cxy.y, t);
            t = fma2(a0p[s], cxy.x, t);

            u64 e = ex2_pair(t);

            su[s] = fma2(e, quv.x, su[s]);
            sv[s] = fma2(e, quv.y, sv[s]);
            sw[s] = fma2(e, qw,    sw[s]);
        }
    }

    // publish this half's partials
    float4* part = g_partial + (size_t)half * NPMAX;
#pragma unroll
    for (int s = 0; s < PTS; s++) {
        int i = g + s * tot;
        if (i < n) {
            float u0, u1, v0, v1, w0, w1;
            unpack2(su[s], u0, u1);
            unpack2(sv[s], v0, v1);
            unpack2(sw[s], w0, w1);
            part[i] = make_float4(u0 + u1, v0 + v1, w0 + w1, 0.f);
        }
    }

    // last-CTA-finishes combine (threadFenceReduction pattern)
    __threadfence();
    __syncthreads();
    __shared__ int ticket;
    if (threadIdx.x == 0) ticket = atomicAdd(&g_count[pb], 1);
    __syncthreads();

    if (ticket == NSPLIT - 1) {
        // all halves for this point-block are published; sum in FIXED order
        // (independent of which CTA finishes -> deterministic output)
#pragma unroll
        for (int s = 0; s < PTS; s++) {
            int i = g + s * tot;
            if (i < n) {
                float4 a = g_partial[i];
                float4 b = g_partial[NPMAX + i];
                float r  = sqrtf(xs[s]);
                float om = 1.f - r;           // base = x * (1 - ||x||)
                out[3*i]   = fmaf(px[s], om, a.x + b.x);
                out[3*i+1] = fmaf(py[s], om, a.y + b.y);
                out[3*i+2] = fmaf(pz[s], om, a.z + b.z);
            }
        }
        if (threadIdx.x == 0) g_count[pb] = 0;   // reset for next launch/replay
    }
}

extern "C" void kernel_launch(void* const* d_in, const int* in_sizes, int n_in,
                              void* d_out, int out_size)
{
    const float* x   = (const float*)d_in[0];
    const float* cen = (const float*)d_in[1];
    const float* cu  = (const float*)d_in[2];
    const float* cv  = (const float*)d_in[3];
    const float* cw  = (const float*)d_in[4];
    float* out = (float*)d_out;

    int n = in_sizes[0] / 3;     // 100000
    int m = in_sizes[2];         // 3375
    int P  = (m + 1) / 2;        // 1688 center pairs (pad to even)
    int Ph = (P + NSPLIT - 1) / NSPLIT;   // 844 pairs per half

    // 3 * float4 + 1 * float2 per pair = 56 B -> 47.25 KB/CTA (2 CTAs/SM)
    size_t smem = (size_t)Ph * (3 * sizeof(float4) + sizeof(float2));
    cudaFuncSetAttribute(rbf_kernel,
                         cudaFuncAttributeMaxDynamicSharedMemorySize,
                         (int)smem);

    // one wave: 2 CTAs/SM on all 148 SMs; slots = 148*352*2 = 104192 (4.2% pad)
    int gridP = (n + BLOCK * PTS - 1) / (BLOCK * PTS);
    if (gridP < NSM) gridP = NSM;
    int tot = gridP * BLOCK;
    rbf_kernel<<<NSPLIT * gridP, BLOCK, smem>>>(x, cen, cu, cv, cw, out,
                                                n, m, Ph, gridP, tot);
}

// round 17
// speedup vs baseline: 1.1013x; 1.1013x over previous
#include <cuda_runtime.h>

// exp(-d2 / (2*0.3^2)) = exp2(-K * d2), K = log2(e) / 0.18
#define KCONST 8.014972449383130f
#define BLOCK 384
#define PTS 2
#define NSPLIT 2
#define NPMAX 131072   // >= n (n = 100000 for this problem)
#define NSM 148        // GB300 SM count

typedef unsigned long long u64;

// partial RBF sums: [half][point] as float4 {u,v,w,pad}
__device__ float4 g_partial[NSPLIT * NPMAX];

__device__ __forceinline__ u64 fma2(u64 a, u64 b, u64 c) {
    u64 d;
    asm("fma.rn.f32x2 %0, %1, %2, %3;" : "=l"(d) : "l"(a), "l"(b), "l"(c));
    return d;
}
__device__ __forceinline__ u64 add2(u64 a, u64 b) {
    u64 d;
    asm("add.rn.f32x2 %0, %1, %2;" : "=l"(d) : "l"(a), "l"(b));
    return d;
}
__device__ __forceinline__ u64 pack2(float lo, float hi) {
    u64 d;
    asm("mov.b64 %0, {%1, %2};" : "=l"(d) : "f"(lo), "f"(hi));
    return d;
}
__device__ __forceinline__ void unpack2(u64 v, float& lo, float& hi) {
    asm("mov.b64 {%0, %1}, %2;" : "=f"(lo), "=f"(hi) : "l"(v));
}
// In-place fp32 ex2 on both packed lanes: "+l" keeps input/output in the
// SAME register pair so the internal movs are pure aliases (elidable).
__device__ __forceinline__ void ex2_pair_ip(u64& t) {
    asm("{\n\t"
        ".reg .f32 a, b;\n\t"
        "mov.b64 {a, b}, %0;\n\t"
        "ex2.approx.ftz.f32 a, a;\n\t"
        "ex2.approx.ftz.f32 b, b;\n\t"
        "mov.b64 %0, {a, b};\n\t"
        "}" : "+l"(t));
}

// One interleaved 64-byte record per center-pair (single smem pointer,
// immediate offsets 0/16/32/48):
//   [ 0) {c0x,c1x, c0y,c1y}
//   [16) {c0z,c1z, cs0,cs1}    cs = -K*|c|^2
//   [32) {u0,u1,  v0,v1}
//   [48) {w0,w1}  [56) pad
struct __align__(16) CRec { float4 A, B, Q; float2 W; float2 pad; };

__global__ __launch_bounds__(BLOCK, NSPLIT)
void rbf_kernel(const float* __restrict__ x, const float* __restrict__ cen,
                const float* __restrict__ cu, const float* __restrict__ cv,
                const float* __restrict__ cw,
                int n, int m, int Ph, int gridP, int tot)
{
    extern __shared__ CRec sr[];

    int pb    = blockIdx.x % gridP;   // point-block
    int half  = blockIdx.x / gridP;   // which center half
    int pbase = half * Ph;            // first center-pair of this half

    for (int p = threadIdx.x; p < Ph; p += BLOCK) {
        int gp = pbase + p;
        float c[2][3], cs[2], qu[2], qv[2], qw[2];
#pragma unroll
        for (int h = 0; h < 2; h++) {
            int e = 2 * gp + h;
            if (e < m) {
                c[h][0] = cen[3*e]; c[h][1] = cen[3*e+1]; c[h][2] = cen[3*e+2];
                cs[h] = -KCONST * (c[h][0]*c[h][0] + c[h][1]*c[h][1] + c[h][2]*c[h][2]);
                qu[h] = cu[e]; qv[h] = cv[e]; qw[h] = cw[e];
            } else {
                // pad: exponent -> -1e30 => ex2 -> 0; coeffs 0 => no contribution
                c[h][0] = c[h][1] = c[h][2] = 0.f;
                cs[h] = -1e30f;
                qu[h] = qv[h] = qw[h] = 0.f;
            }
        }
        sr[p].A = make_float4(c[0][0], c[1][0], c[0][1], c[1][1]);
        sr[p].B = make_float4(c[0][2], c[1][2], cs[0], cs[1]);
        sr[p].Q = make_float4(qu[0], qu[1], qv[0], qv[1]);
        sr[p].W = make_float2(qw[0], qw[1]);
    }
    __syncthreads();

    int g = pb * BLOCK + threadIdx.x;

    u64 a0p[PTS], a1p[PTS], a2p[PTS], bbp[PTS];
#pragma unroll
    for (int s = 0; s < PTS; s++) {
        int i = g + s * tot;
        int ic = (i < n) ? i : 0;     // clamp loads; stores guarded below
        float x0 = x[3*ic], x1 = x[3*ic+1], x2 = x[3*ic+2];
        float a0 = 2.f * KCONST * x0;
        float a1 = 2.f * KCONST * x1;
        float a2 = 2.f * KCONST * x2;
        float bb = -KCONST * (x0*x0 + x1*x1 + x2*x2);
        a0p[s] = pack2(a0, a0);
        a1p[s] = pack2(a1, a1);
        a2p[s] = pack2(a2, a2);
        bbp[s] = pack2(bb, bb);
    }

    u64 su[PTS], sv[PTS], sw[PTS];   // packed over the 2 center lanes
#pragma unroll
    for (int s = 0; s < PTS; s++) { su[s] = 0; sv[s] = 0; sw[s] = 0; }

    const CRec* rp = sr;
#pragma unroll 2
    for (int p = 0; p < Ph; p++, rp++) {
        // broadcast loads from one pointer at fixed offsets
        ulonglong2 cxy = *(const ulonglong2*)&rp->A;  // {c0x,c1x},{c0y,c1y}
        ulonglong2 czs = *(const ulonglong2*)&rp->B;  // {c0z,c1z},{cs0,cs1}
        ulonglong2 quv = *(const ulonglong2*)&rp->Q;  // {u0,u1},{v0,v1}
        u64        qw  = *(const u64*)&rp->W;         // {w0,w1}

#pragma unroll
        for (int s = 0; s < PTS; s++) {
            // t = 2K*x.c - K|x|^2 - K|c|^2  (packed over 2 centers)
            u64 t = add2(czs.y, bbp[s]);
            t = fma2(a2p[s], czs.x, t);
            t = fma2(a1p[s], cxy.y, t);
            t = fma2(a0p[s], cxy.x, t);

            ex2_pair_ip(t);   // t := 2^t, in place

            su[s] = fma2(t, quv.x, su[s]);
            sv[s] = fma2(t, quv.y, sv[s]);
            sw[s] = fma2(t, qw,    sw[s]);
        }
    }

    float4* part = g_partial + (size_t)half * NPMAX;
#pragma unroll
    for (int s = 0; s < PTS; s++) {
        int i = g + s * tot;
        if (i < n) {
            float u0, u1, v0, v1, w0, w1;
            unpack2(su[s], u0, u1);
            unpack2(sv[s], v0, v1);
            unpack2(sw[s], w0, w1);
            part[i] = make_float4(u0 + u1, v0 + v1, w0 + w1, 0.f);
        }
    }
}

__global__ void combine_kernel(const float* __restrict__ x,
                               float* __restrict__ out, int n)
{
    int i = blockIdx.x * blockDim.x + threadIdx.x;
    if (i >= n) return;
    float x0 = x[3*i], x1 = x[3*i+1], x2 = x[3*i+2];
    float r  = sqrtf(x0*x0 + x1*x1 + x2*x2);
    float om = 1.f - r;                       // base = x * (1 - ||x||)
    float4 a = g_partial[i];
    float4 b = g_partial[NPMAX + i];
    out[3*i]   = fmaf(x0, om, a.x + b.x);
    out[3*i+1] = fmaf(x1, om, a.y + b.y);
    out[3*i+2] = fmaf(x2, om, a.z + b.z);
}

extern "C" void kernel_launch(void* const* d_in, const int* in_sizes, int n_in,
                              void* d_out, int out_size)
{
    const float* x   = (const float*)d_in[0];
    const float* cen = (const float*)d_in[1];
    const float* cu  = (const float*)d_in[2];
    const float* cv  = (const float*)d_in[3];
    const float* cw  = (const float*)d_in[4];
    float* out = (float*)d_out;

    int n = in_sizes[0] / 3;     // 100000
    int m = in_sizes[2];         // 3375
    int P  = (m + 1) / 2;        // 1688 center pairs (pad to even)
    int Ph = (P + NSPLIT - 1) / NSPLIT;   // 844 pairs per half

    // 64 B per pair -> 52.75 KB/CTA (2 CTAs/SM = 105.5 KB)
    size_t smem = (size_t)Ph * sizeof(CRec);
    cudaFuncSetAttribute(rbf_kernel,
                         cudaFuncAttributeMaxDynamicSharedMemorySize,
                         (int)smem);

    // one wave: 2 CTAs/SM on all 148 SMs (R12-proven geometry)
    int gridP = (n + BLOCK * PTS - 1) / (BLOCK * PTS);
    if (gridP < NSM) gridP = NSM;
    int tot = gridP * BLOCK;
    rbf_kernel<<<NSPLIT * gridP, BLOCK, smem>>>(x, cen, cu, cv, cw,
                                                n, m, Ph, gridP, tot);

    combine_kernel<<<(n + 255) / 256, 256>>>(x, out, n);
}